// round 3
// baseline (speedup 1.0000x reference)
#include <cuda_runtime.h>
#include <cstdint>

// GRU: B=128, T=4096, I=6, H=32, O=2. One CTA per sequence, 5 warps:
//   warp 0: r-dot + z-dot + assembly (critical path)
//   warp 1: n-dot -> s_ns (cross-warp via named bar 1)
//   warp 2: FC output, one chunk behind
//   warps 3,4: gx producers, one chunk ahead
// Named barriers (64 threads, warps 0-1): bar1 publishes ns, bar2 publishes h.

#define Bq 128
#define Tq 4096
#define Iq 6
#define Hq 32
#define Oq 2
#define CH 32
#define NCH (Tq / CH)
#define HPAD 36   // 144B rows: 16B-aligned for ld.shared.v2.b64

#define KRf (-1.4426950408889634f)   // -log2(e): sigmoid(v)=rcp(1+ex2(KR*v))
#define KNf ( 2.8853900817779268f)   // 2*log2(e): tanh(v)=1-2*rcp(1+ex2(KN*v))

typedef unsigned long long u64;

__device__ __forceinline__ float ex2a(float x) { float y; asm("ex2.approx.f32 %0, %1;" : "=f"(y) : "f"(x)); return y; }
__device__ __forceinline__ float rcpa(float x) { float y; asm("rcp.approx.f32 %0, %1;" : "=f"(y) : "f"(x)); return y; }

__device__ __forceinline__ u64 pk2(float lo, float hi) { u64 r; asm("mov.b64 %0, {%1, %2};" : "=l"(r) : "f"(lo), "f"(hi)); return r; }
__device__ __forceinline__ void upk2(u64 v, float& lo, float& hi) { asm("mov.b64 {%0, %1}, %2;" : "=f"(lo), "=f"(hi) : "l"(v)); }
__device__ __forceinline__ u64 f2fma(u64 a, u64 b, u64 c) { u64 d; asm("fma.rn.f32x2 %0, %1, %2, %3;" : "=l"(d) : "l"(a), "l"(b), "l"(c)); return d; }
__device__ __forceinline__ u64 f2add(u64 a, u64 b) { u64 d; asm("add.rn.f32x2 %0, %1, %2;" : "=l"(d) : "l"(a), "l"(b)); return d; }
__device__ __forceinline__ uint32_t saddr(const void* p) {
    uint32_t a;
    asm("{ .reg .u64 t; cvta.to.shared.u64 t, %1; cvt.u32.u64 %0, t; }" : "=r"(a) : "l"(p));
    return a;
}
__device__ __forceinline__ void lds128v(uint32_t a, u64& v0, u64& v1) {
    asm volatile("ld.shared.v2.b64 {%0, %1}, [%2];" : "=l"(v0), "=l"(v1) : "r"(a));
}
__device__ __forceinline__ float lds32v(uint32_t a) { float v; asm volatile("ld.shared.f32 %0, [%1];" : "=f"(v) : "r"(a)); return v; }
__device__ __forceinline__ void sts32v(uint32_t a, float v) { asm volatile("st.shared.f32 [%0], %1;" :: "r"(a), "f"(v)); }
__device__ __forceinline__ void sts128f(uint32_t a, float x, float y, float z, float w) {
    asm volatile("st.shared.v4.f32 [%0], {%1, %2, %3, %4};" :: "r"(a), "f"(x), "f"(y), "f"(z), "f"(w));
}
__device__ __forceinline__ void bar1() { asm volatile("bar.sync 1, 64;" ::: "memory"); }
__device__ __forceinline__ void bar2() { asm volatile("bar.sync 2, 64;" ::: "memory"); }

// horizontal sum of 4 packed-f32x2 accumulators
__device__ __forceinline__ float hsum4(u64 a0, u64 a1, u64 a2, u64 a3) {
    u64 s = f2add(f2add(a0, a1), f2add(a2, a3));
    float lo, hi; upk2(s, lo, hi);
    return lo + hi;
}

__global__ void __launch_bounds__(160, 1) gru_seq_kernel(
    const float* __restrict__ x,        // [B, T, I]
    const int*   __restrict__ lengths,  // [B]
    const float* __restrict__ w_ih,     // [3H, I]
    const float* __restrict__ w_hh,     // [3H, H]
    const float* __restrict__ b_ih,     // [3H]
    const float* __restrict__ b_hh,     // [3H]
    const float* __restrict__ fc_w,     // [O, H]
    const float* __restrict__ fc_b,     // [O]
    float* __restrict__ out)            // [B, T, O]
{
    __shared__ __align__(16) float s_gx[2][CH][Hq][4];  // (pr,pz,pn,0) per (step,lane)
    __shared__ __align__(16) float s_h[2][CH][HPAD];    // h ring
    __shared__ __align__(16) float s_ns[Hq];            // n-dot cross-warp slot

    const int lane = threadIdx.x & 31;
    const int warp = threadIdx.x >> 5;
    const int b = blockIdx.x;
    const int L = lengths[b];

    const uint32_t hbase  = saddr(&s_h[0][0][0]);
    const uint32_t gxbase = saddr(&s_gx[0][0][0][0]);
    const uint32_t nsaddr = saddr(&s_ns[0]) + lane * 4;

    if (warp == 0) {
        // ================= A: r,z dots + assembly =================
        u64 wr[16], wz[16];
        const float* rr = w_hh + lane * Hq;
        const float* rz = w_hh + (Hq + lane) * Hq;
#pragma unroll
        for (int j = 0; j < 16; j++) {
            wr[j] = pk2(KRf * rr[2 * j], KRf * rr[2 * j + 1]);
            wz[j] = pk2(KRf * rz[2 * j], KRf * rz[2 * j + 1]);
        }
        s_h[1][CH - 1][lane] = 0.0f;  // initial hidden state row
        float hk = 0.f;
        uint32_t hprev = hbase + ((1 * CH + (CH - 1)) * HPAD) * 4;

        for (int c = 0; c < NCH; c++) {
            __syncthreads();
            int nst = L - c * CH;
            nst = nst < 0 ? 0 : (nst > CH ? CH : nst);
            uint32_t gxa = gxbase + ((c & 1) * CH * Hq) * 16 + lane * 16;
            uint32_t hrow = hbase + ((c & 1) * CH * HPAD) * 4;
#pragma unroll 1
            for (int s = 0; s < nst; s++) {
                u64 g01, g23;
                lds128v(gxa, g01, g23);
                u64 hp[16];
#pragma unroll
                for (int j = 0; j < 8; j++) lds128v(hprev + 16 * j, hp[2 * j], hp[2 * j + 1]);
                float pr, pz, pn, pd;
                upk2(g01, pr, pz);
                upk2(g23, pn, pd);

                u64 ar0 = pk2(pr, 0.f), ar1 = 0ull, ar2 = 0ull, ar3 = 0ull;
                u64 az0 = pk2(pz, 0.f), az1 = 0ull, az2 = 0ull, az3 = 0ull;
#pragma unroll
                for (int j = 0; j < 16; j += 4) {   // r first: r is on the critical path
                    ar0 = f2fma(wr[j], hp[j], ar0);
                    ar1 = f2fma(wr[j + 1], hp[j + 1], ar1);
                    ar2 = f2fma(wr[j + 2], hp[j + 2], ar2);
                    ar3 = f2fma(wr[j + 3], hp[j + 3], ar3);
                }
#pragma unroll
                for (int j = 0; j < 16; j += 4) {
                    az0 = f2fma(wz[j], hp[j], az0);
                    az1 = f2fma(wz[j + 1], hp[j + 1], az1);
                    az2 = f2fma(wz[j + 2], hp[j + 2], az2);
                    az3 = f2fma(wz[j + 3], hp[j + 3], az3);
                }
                float rs = hsum4(ar0, ar1, ar2, ar3);   // = KR*(gxr+bhr+dot_r)
                float zs = hsum4(az0, az1, az2, az3);   // = KR*(gxz+bhz+dot_z)
                float er = ex2a(rs);                    // MUFUs in flight across the bar
                float ez = ex2a(zs);

                bar1();                                  // warp1's ns now visible
                float ns = lds32v(nsaddr);              // = KN*(bhn + dot_n)

                float r = rcpa(1.0f + er);
                float z = rcpa(1.0f + ez);
                float omz = 1.0f - z;
                float c0 = fmaf(z, hk, omz);            // omz + z*h
                float c1 = -2.0f * omz;
                float q = rcpa(1.0f + ex2a(fmaf(r, ns, pn)));
                hk = fmaf(c1, q, c0);                    // h_new

                sts32v(hrow + lane * 4, hk);
                bar2();                                  // publish h
                hprev = hrow;
                hrow += HPAD * 4;
                gxa += Hq * 16;
            }
        }
        __syncthreads();
    } else if (warp == 1) {
        // ================= B: n-dot =================
        u64 wn[16];
        const float* rn = w_hh + (2 * Hq + lane) * Hq;
#pragma unroll
        for (int j = 0; j < 16; j++)
            wn[j] = pk2(KNf * rn[2 * j], KNf * rn[2 * j + 1]);
        const u64 bhn_pk = pk2(KNf * b_hh[2 * Hq + lane], 0.0f);
        uint32_t hprev = hbase + ((1 * CH + (CH - 1)) * HPAD) * 4;

        for (int c = 0; c < NCH; c++) {
            __syncthreads();
            int nst = L - c * CH;
            nst = nst < 0 ? 0 : (nst > CH ? CH : nst);
            uint32_t hrow = hbase + ((c & 1) * CH * HPAD) * 4;
#pragma unroll 1
            for (int s = 0; s < nst; s++) {
                u64 hp[16];
#pragma unroll
                for (int j = 0; j < 8; j++) lds128v(hprev + 16 * j, hp[2 * j], hp[2 * j + 1]);
                u64 an0 = bhn_pk, an1 = 0ull, an2 = 0ull, an3 = 0ull;
#pragma unroll
                for (int j = 0; j < 16; j += 4) {
                    an0 = f2fma(wn[j], hp[j], an0);
                    an1 = f2fma(wn[j + 1], hp[j + 1], an1);
                    an2 = f2fma(wn[j + 2], hp[j + 2], an2);
                    an3 = f2fma(wn[j + 3], hp[j + 3], an3);
                }
                float ns = hsum4(an0, an1, an2, an3);
                sts32v(nsaddr, ns);
                bar1();                                  // publish ns
                bar2();                                  // wait for h
                hprev = hrow;
                hrow += HPAD * 4;
            }
        }
        __syncthreads();
    } else if (warp == 2) {
        // ================= FC output, one chunk behind =================
        for (int c = 0; c < NCH; c++) {
            __syncthreads();
            if (c > 0) {
                const int cp = c - 1;
                const int t = cp * CH + lane;
                float o0 = __ldg(fc_b + 0);
                float o1 = __ldg(fc_b + 1);
                if (t < L) {
                    const float* hr = &s_h[cp & 1][lane][0];
#pragma unroll
                    for (int j = 0; j < Hq; j++) {
                        float hv = hr[j];
                        o0 = fmaf(__ldg(fc_w + j), hv, o0);
                        o1 = fmaf(__ldg(fc_w + Hq + j), hv, o1);
                    }
                }
                float2 v = make_float2(o0, o1);
                *reinterpret_cast<float2*>(out + ((size_t)b * Tq + t) * Oq) = v;
            }
        }
        __syncthreads();
        {   // epilogue: last chunk
            const int cp = NCH - 1;
            const int t = cp * CH + lane;
            float o0 = __ldg(fc_b + 0);
            float o1 = __ldg(fc_b + 1);
            if (t < L) {
                const float* hr = &s_h[cp & 1][lane][0];
#pragma unroll
                for (int j = 0; j < Hq; j++) {
                    float hv = hr[j];
                    o0 = fmaf(__ldg(fc_w + j), hv, o0);
                    o1 = fmaf(__ldg(fc_w + Hq + j), hv, o1);
                }
            }
            float2 v = make_float2(o0, o1);
            *reinterpret_cast<float2*>(out + ((size_t)b * Tq + t) * Oq) = v;
        }
    } else {
        // ================= producers (warps 3,4), one chunk ahead =================
        float wiA[Iq], wiB[Iq], wiC[Iq];
#pragma unroll
        for (int i = 0; i < Iq; i++) {
            wiA[i] = w_ih[lane * Iq + i];
            wiB[i] = w_ih[(Hq + lane) * Iq + i];
            wiC[i] = w_ih[(2 * Hq + lane) * Iq + i];
        }
        const float biA = b_ih[lane] + b_hh[lane];
        const float biB = b_ih[Hq + lane] + b_hh[Hq + lane];
        const float biC = b_ih[2 * Hq + lane];
        const int s0 = (warp == 4) ? (CH / 2) : 0;

        // prologue: chunk 0
        {
            const float* xp = x + ((size_t)b * Tq + s0) * Iq;
            uint32_t ga = gxbase + (s0 * Hq + lane) * 16;
#pragma unroll 1
            for (int s = 0; s < CH / 2; s++) {
                float xv[Iq];
#pragma unroll
                for (int i = 0; i < Iq; i++) xv[i] = xp[i];
                float gr = biA, gz = biB, gn = biC;
#pragma unroll
                for (int i = 0; i < Iq; i++) {
                    gr = fmaf(wiA[i], xv[i], gr);
                    gz = fmaf(wiB[i], xv[i], gz);
                    gn = fmaf(wiC[i], xv[i], gn);
                }
                sts128f(ga, KRf * gr, KRf * gz, KNf * gn, 0.0f);
                ga += Hq * 16;
                xp += Iq;
            }
        }
        for (int c = 0; c < NCH; c++) {
            __syncthreads();
            const int cc = c + 1;
            if (cc < NCH) {
                const float* xp = x + ((size_t)b * Tq + cc * CH + s0) * Iq;
                uint32_t ga = gxbase + (((cc & 1) * CH + s0) * Hq + lane) * 16;
#pragma unroll 1
                for (int s = 0; s < CH / 2; s++) {
                    float xv[Iq];
#pragma unroll
                    for (int i = 0; i < Iq; i++) xv[i] = xp[i];
                    float gr = biA, gz = biB, gn = biC;
#pragma unroll
                    for (int i = 0; i < Iq; i++) {
                        gr = fmaf(wiA[i], xv[i], gr);
                        gz = fmaf(wiB[i], xv[i], gz);
                        gn = fmaf(wiC[i], xv[i], gn);
                    }
                    sts128f(ga, KRf * gr, KRf * gz, KNf * gn, 0.0f);
                    ga += Hq * 16;
                    xp += Iq;
                }
            }
        }
        __syncthreads();
    }
}

extern "C" void kernel_launch(void* const* d_in, const int* in_sizes, int n_in,
                              void* d_out, int out_size) {
    const float* x       = (const float*)d_in[0];
    const int*   lengths = (const int*)d_in[1];
    const float* w_ih    = (const float*)d_in[2];
    const float* w_hh    = (const float*)d_in[3];
    const float* b_ih    = (const float*)d_in[4];
    const float* b_hh    = (const float*)d_in[5];
    const float* fc_w    = (const float*)d_in[6];
    const float* fc_b    = (const float*)d_in[7];
    float* out = (float*)d_out;

    gru_seq_kernel<<<Bq, 160>>>(x, lengths, w_ih, w_hh, b_ih, b_hh, fc_w, fc_b, out);
}